// round 13
// baseline (speedup 1.0000x reference)
#include <cuda_runtime.h>
#include <math.h>

// Single kernel, zero synchronization (converged configuration).
// - x row3 loaded FIRST; its passthrough store issues as soon as that load
//   returns (depends on the first scoreboard slot, not the last) -> earliest
//   possible write-stream start per warp
// - remaining 3 loads front-batched behind it
// - per-thread closed-form Rodrigues build, hidden under load latency
// - 256 threads, 6 blocks/SM, ~40 regs, no smem, no barrier
//
// x and out are [4, N] row-major; processed as float4 columns (n4 = N/4).
// Matrix rows 0..2 are (R_i0, R_i1, R_i2, t_i); row 3 is [0,0,0,1] so
// out row3 = x row3.

__device__ __forceinline__ void build_M(const float* __restrict__ w,
                                        const float* __restrict__ v,
                                        const float* __restrict__ theta_p,
                                        float4& m0, float4& m1, float4& m2) {
    const float wx = __ldg(&w[0]), wy = __ldg(&w[1]), wz = __ldg(&w[2]);
    const float vx = __ldg(&v[0]), vy = __ldg(&v[1]), vz = __ldg(&v[2]);
    const float th = __ldg(&theta_p[0]);
    const float s = sinf(th);
    const float c = cosf(th);
    const float a = 1.0f - c;      // (1 - cos)
    const float b = th - s;        // (theta - sin)

    // KK = K@K for K = skew(w)
    const float xx = wx*wx, yy = wy*wy, zz = wz*wz;
    const float xy = wx*wy, xz = wx*wz, yz = wy*wz;

    // R = I + s*K + a*KK
    const float R00 = 1.0f - a*(yy + zz);
    const float R01 = -s*wz + a*xy;
    const float R02 =  s*wy + a*xz;
    const float R10 =  s*wz + a*xy;
    const float R11 = 1.0f - a*(xx + zz);
    const float R12 = -s*wx + a*yz;
    const float R20 = -s*wy + a*xz;
    const float R21 =  s*wx + a*yz;
    const float R22 = 1.0f - a*(xx + yy);

    // V = I*th + a*K + b*KK ;  t = V @ v
    const float V00 = th - b*(yy + zz);
    const float V01 = -a*wz + b*xy;
    const float V02 =  a*wy + b*xz;
    const float V10 =  a*wz + b*xy;
    const float V11 = th - b*(xx + zz);
    const float V12 = -a*wx + b*yz;
    const float V20 = -a*wy + b*xz;
    const float V21 =  a*wx + b*yz;
    const float V22 = th - b*(xx + yy);

    const float t0 = V00*vx + V01*vy + V02*vz;
    const float t1 = V10*vx + V11*vy + V12*vz;
    const float t2 = V20*vx + V21*vy + V22*vz;

    m0 = make_float4(R00, R01, R02, t0);
    m1 = make_float4(R10, R11, R12, t1);
    m2 = make_float4(R20, R21, R22, t2);
}

__global__ void __launch_bounds__(256, 6)
se3_nosync(const float4* __restrict__ x, float4* __restrict__ out,
           const float* __restrict__ w, const float* __restrict__ v,
           const float* __restrict__ theta_p, unsigned n4) {
    const unsigned i = blockIdx.x * blockDim.x + threadIdx.x;
    if (i >= n4) return;

    // 32-bit offsets: max element offset 4*n4 = N < 2^31.
    const unsigned i1 = i + n4;
    const unsigned i2 = i1 + n4;
    const unsigned i3 = i2 + n4;

    // Row 3 first: its passthrough store can issue as soon as this load lands.
    const float4 x3 = __ldcg(&x[i3]);
    const float4 x0 = __ldcg(&x[i]);
    const float4 x1 = __ldcg(&x[i1]);
    const float4 x2 = __ldcg(&x[i2]);

    // Earliest possible write-stream start (depends only on the first load).
    __stcs(&out[i3], x3);

    // Per-thread matrix build, hidden under the load latency.
    float4 m0, m1, m2;
    build_M(w, v, theta_p, m0, m1, m2);

    float4 r0, r1, r2;
    r0.x = m0.x*x0.x + m0.y*x1.x + m0.z*x2.x + m0.w*x3.x;
    r0.y = m0.x*x0.y + m0.y*x1.y + m0.z*x2.y + m0.w*x3.y;
    r0.z = m0.x*x0.z + m0.y*x1.z + m0.z*x2.z + m0.w*x3.z;
    r0.w = m0.x*x0.w + m0.y*x1.w + m0.z*x2.w + m0.w*x3.w;
    __stcs(&out[i], r0);

    r1.x = m1.x*x0.x + m1.y*x1.x + m1.z*x2.x + m1.w*x3.x;
    r1.y = m1.x*x0.y + m1.y*x1.y + m1.z*x2.y + m1.w*x3.y;
    r1.z = m1.x*x0.z + m1.y*x1.z + m1.z*x2.z + m1.w*x3.z;
    r1.w = m1.x*x0.w + m1.y*x1.w + m1.z*x2.w + m1.w*x3.w;
    __stcs(&out[i1], r1);

    r2.x = m2.x*x0.x + m2.y*x1.x + m2.z*x2.x + m2.w*x3.x;
    r2.y = m2.x*x0.y + m2.y*x1.y + m2.z*x2.y + m2.w*x3.y;
    r2.z = m2.x*x0.z + m2.y*x1.z + m2.z*x2.z + m2.w*x3.z;
    r2.w = m2.x*x0.w + m2.y*x1.w + m2.z*x2.w + m2.w*x3.w;
    __stcs(&out[i2], r2);
}

extern "C" void kernel_launch(void* const* d_in, const int* in_sizes, int n_in,
                              void* d_out, int out_size) {
    const float* x     = (const float*)d_in[0];   // [4, N]
    const float* w     = (const float*)d_in[1];   // [3]
    const float* v     = (const float*)d_in[2];   // [3]
    const float* theta = (const float*)d_in[3];   // scalar

    const unsigned N  = (unsigned)(in_sizes[0] / 4);   // columns
    const unsigned n4 = N / 4;                         // float4 columns per row

    const int threads = 256;
    const int blocks  = (int)((n4 + threads - 1) / threads);
    se3_nosync<<<blocks, threads>>>((const float4*)x, (float4*)d_out,
                                    w, v, theta, n4);
}